// round 2
// baseline (speedup 1.0000x reference)
#include <cuda_runtime.h>
#include <cuda_fp16.h>
#include <cstdint>

#define TOKENS 8192
#define OUT_F  4096
#define IN_F   4096

// Scratch (allocation-guard-safe __device__ globals): 64 MB each.
__device__ __half g_W[(size_t)OUT_F * IN_F];
__device__ __half g_X[(size_t)TOKENS * IN_F];

// ---------------------------------------------------------------------------
// Convert x: harness delivers float32; GEMM wants fp16. 8 elems/thread.
// ---------------------------------------------------------------------------
__global__ void convert_x_kernel(const float* __restrict__ xf) {
    size_t t = (size_t)blockIdx.x * blockDim.x + threadIdx.x;
    float4 f0 = ((const float4*)xf)[2 * t];
    float4 f1 = ((const float4*)xf)[2 * t + 1];
    __half2 h[4];
    h[0] = __floats2half2_rn(f0.x, f0.y);
    h[1] = __floats2half2_rn(f0.z, f0.w);
    h[2] = __floats2half2_rn(f1.x, f1.y);
    h[3] = __floats2half2_rn(f1.z, f1.w);
    ((int4*)g_X)[t] = *(int4*)h;
}

// ---------------------------------------------------------------------------
// Dequant: packed nibbles (one byte per int32) -> fp16 W [OUT_F, IN_F].
// Element e: blk1 = e>>6, blk2 = e>>8. Byte p -> elems 2p (lo), 2p+1 (hi).
// Thread t: packed bytes 4t..4t+3 (one int4 load) -> elems 8t..8t+7 (one
// int4 store). All 4 bytes share blk1 = (4t)>>5 and blk2 = (4t)>>7.
// ---------------------------------------------------------------------------
__global__ void dequant_kernel(const int* __restrict__ qw,
                               const int* __restrict__ absmax1,
                               const float* __restrict__ code1,
                               const float* __restrict__ offset1,
                               const float* __restrict__ absmax2,
                               const float* __restrict__ code2) {
    int t = blockIdx.x * blockDim.x + threadIdx.x;
    int p0 = t * 4;
    int4 q4 = ((const int4*)qw)[t];
    int blk1 = p0 >> 5;
    int blk2 = p0 >> 7;
    float scale = ((float)absmax1[blk1] / code1[blk1]) *
                  (absmax2[blk2] / code2[blk2]);
    float off = offset1[blk1];
    int b[4] = {q4.x, q4.y, q4.z, q4.w};
    __half2 o[4];
#pragma unroll
    for (int j = 0; j < 4; j++) {
        float lo = (float)(b[j] & 15);
        float hi = (float)((b[j] >> 4) & 15);
        o[j] = __floats2half2_rn((lo - off) * scale, (hi - off) * scale);
    }
    ((int4*)g_W)[t] = *(int4*)o;   // elements [8t, 8t+8)
}

// ---------------------------------------------------------------------------
// GEMM: out[M=8192, N=4096](f32) = X[M,K=4096](f16) * W[N,K](f16)^T
// mma.sync m16n8k16 f32 accum, BM=128 BN=128 BK=32, 2-stage cp.async.
// ---------------------------------------------------------------------------
#define BM 128
#define BN 128
#define BK 32
#define PAD 8
#define KTILES (IN_F / BK)

__device__ __forceinline__ uint32_t smem_u32(const void* p) {
    return (uint32_t)__cvta_generic_to_shared(p);
}
__device__ __forceinline__ void cp_async16(uint32_t s, const void* g) {
    asm volatile("cp.async.cg.shared.global [%0], [%1], 16;\n" :: "r"(s), "l"(g));
}
__device__ __forceinline__ void cp_commit() {
    asm volatile("cp.async.commit_group;\n");
}
template<int N_> __device__ __forceinline__ void cp_wait() {
    asm volatile("cp.async.wait_group %0;\n" :: "n"(N_));
}
__device__ __forceinline__ void ldm_x4(uint32_t& r0, uint32_t& r1,
                                       uint32_t& r2, uint32_t& r3, uint32_t a) {
    asm volatile("ldmatrix.sync.aligned.m8n8.x4.shared.b16 {%0,%1,%2,%3}, [%4];"
                 : "=r"(r0), "=r"(r1), "=r"(r2), "=r"(r3) : "r"(a));
}

__global__ void __launch_bounds__(256, 2)
gemm_kernel(float* __restrict__ O) {
    __shared__ __align__(16) __half As[2][BM][BK + PAD];
    __shared__ __align__(16) __half Bs[2][BN][BK + PAD];

    const int tid  = threadIdx.x;
    const int warp = tid >> 5;
    const int lane = tid & 31;
    const int wm   = warp & 3;   // 4 warps over M: 32 rows each
    const int wn   = warp >> 2;  // 2 warps over N: 64 cols each
    const int bm   = blockIdx.y * BM;
    const int bn   = blockIdx.x * BN;

    // Per-tile: 512 chunks of 16B; 256 threads x 2 chunks.
    const int r0c = tid >> 2;            // rows 0..63
    const int c0c = (tid & 3) * 8;       // half-offset in row
    const int r1c = (tid + 256) >> 2;    // rows 64..127
    const int c1c = c0c;

#define LOAD_TILES(stage, kt)                                                  \
    do {                                                                       \
        int k0 = (kt) * BK;                                                    \
        cp_async16(smem_u32(&As[stage][r0c][c0c]),                             \
                   g_X + (size_t)(bm + r0c) * IN_F + k0 + c0c);                \
        cp_async16(smem_u32(&Bs[stage][r0c][c0c]),                             \
                   g_W + (size_t)(bn + r0c) * IN_F + k0 + c0c);                \
        cp_async16(smem_u32(&As[stage][r1c][c1c]),                             \
                   g_X + (size_t)(bm + r1c) * IN_F + k0 + c1c);                \
        cp_async16(smem_u32(&Bs[stage][r1c][c1c]),                             \
                   g_W + (size_t)(bn + r1c) * IN_F + k0 + c1c);                \
    } while (0)

    float acc[2][8][4] = {};

    LOAD_TILES(0, 0); cp_commit();
    LOAD_TILES(1, 1); cp_commit();
    cp_wait<1>(); __syncthreads();

    for (int kt = 0; kt < KTILES; kt++) {
        const int st = kt & 1;
#pragma unroll
        for (int kk = 0; kk < BK; kk += 16) {
            uint32_t a[2][4];
#pragma unroll
            for (int im = 0; im < 2; im++) {
                int row = wm * 32 + im * 16 + (lane & 15);
                int col = kk + (lane >> 4) * 8;
                ldm_x4(a[im][0], a[im][1], a[im][2], a[im][3],
                       smem_u32(&As[st][row][col]));
            }
            uint32_t b[8][2];
#pragma unroll
            for (int ib = 0; ib < 4; ib++) {
                int row = wn * 64 + ib * 16 + (lane & 7) + ((lane >> 4) << 3);
                int col = kk + ((lane >> 3) & 1) * 8;
                uint32_t q0, q1, q2, q3;
                ldm_x4(q0, q1, q2, q3, smem_u32(&Bs[st][row][col]));
                b[ib * 2][0] = q0; b[ib * 2][1] = q1;
                b[ib * 2 + 1][0] = q2; b[ib * 2 + 1][1] = q3;
            }
#pragma unroll
            for (int im = 0; im < 2; im++)
#pragma unroll
                for (int in = 0; in < 8; in++) {
                    asm volatile(
                        "mma.sync.aligned.m16n8k16.row.col.f32.f16.f16.f32 "
                        "{%0,%1,%2,%3},{%4,%5,%6,%7},{%8,%9},{%0,%1,%2,%3};"
                        : "+f"(acc[im][in][0]), "+f"(acc[im][in][1]),
                          "+f"(acc[im][in][2]), "+f"(acc[im][in][3])
                        : "r"(a[im][0]), "r"(a[im][1]),
                          "r"(a[im][2]), "r"(a[im][3]),
                          "r"(b[in][0]), "r"(b[in][1]));
                }
        }
        __syncthreads();
        if (kt + 2 < KTILES) LOAD_TILES(st, kt + 2);
        cp_commit();
        cp_wait<1>();
        __syncthreads();
    }

    // Epilogue: round through fp16 (reference is fp16), store as f32.
    const int gid  = lane >> 2;
    const int tid4 = lane & 3;
#pragma unroll
    for (int im = 0; im < 2; im++)
#pragma unroll
        for (int in = 0; in < 8; in++) {
            int n = bn + wn * 64 + in * 8 + tid4 * 2;
#pragma unroll
            for (int r = 0; r < 2; r++) {
                int m = bm + wm * 32 + im * 16 + gid + r * 8;
                float2 v;
                v.x = __half2float(__float2half_rn(acc[im][in][r * 2]));
                v.y = __half2float(__float2half_rn(acc[im][in][r * 2 + 1]));
                *(float2*)(O + (size_t)m * OUT_F + n) = v;
            }
        }
#undef LOAD_TILES
}

// ---------------------------------------------------------------------------
// Inputs (metadata order): x f32, quantized_weight i32, quant_absmax i32,
// quant_code f32, quant_offset f32, state2_absmax f32, state2_code f32.
// Output: float32 [TOKENS, OUT_F].
// ---------------------------------------------------------------------------
extern "C" void kernel_launch(void* const* d_in, const int* in_sizes, int n_in,
                              void* d_out, int out_size) {
    const float* x    = (const float*)d_in[0];
    const int*   qw   = (const int*)d_in[1];
    const int*   am1  = (const int*)d_in[2];
    const float* cd1  = (const float*)d_in[3];
    const float* of1  = (const float*)d_in[4];
    const float* am2  = (const float*)d_in[5];
    const float* cd2  = (const float*)d_in[6];
    float* out = (float*)d_out;

    convert_x_kernel<<<(TOKENS * IN_F / 8) / 256, 256>>>(x);

    const int P = OUT_F * IN_F / 2;              // packed bytes
    dequant_kernel<<<P / 4 / 256, 256>>>(qw, am1, cd1, of1, am2, cd2);

    dim3 grid(OUT_F / BN, TOKENS / BM);
    gemm_kernel<<<grid, 256>>>(out);
}